// round 15
// baseline (speedup 1.0000x reference)
#include <cuda_runtime.h>
#include <cuda_bf16.h>
#include <math_constants.h>
#include <cstdint>

#define NB      8192
#define ND      128
#define MARGIN  1.0f
#define NTILE   1056                 // {(it,jtc): 0<=jtc<32, 2*jtc<=it<64}

// CTA tile: 128 rows x 256 cols. Warp tile: 64x64 (2x4 warp grid).
#define RSTRIDE 136                  // padded row stride in halves (272B)
#define BUFA    (128 * RSTRIDE * 2)  // 34816
#define BUFG    (256 * RSTRIDE * 2)  // 69632

#define OFF_LI    0                  // int[128]
#define OFF_LJ    512                // int[256]
#define OFF_SQI   1536               // float[128]
#define OFF_SQJ   2048               // float[256]
#define OFF_SCR_R 3072               // float[128][4]
#define OFF_SCR_C 5120               // float[256][2]
#define OFF_BUFA  7168
#define OFF_BUFB  (OFF_BUFA + BUFA)  // 41984
#define SMEM_SZ   (OFF_BUFB + BUFG)  // 111616

#define PPCAP   131072               // positive-pair entry capacity
#define PL_GRID 296                  // pairloss blocks

// -------- scratch in device globals (no allocation allowed) --------
__device__ unsigned int g_hardest[NB];
__device__ float        g_sq[NB];
__device__ int          g_labels[NB];
__device__ float        g_total;
__device__ int          g_count;
__device__ int          g_done;
__device__ __nv_bfloat16 g_eb[NB * ND];          // bf16 embeddings
__device__ unsigned long long g_pp[PPCAP];       // packed (anchor<<32 | f32bits(d_pos))
__device__ int          g_pp_n;

__device__ __forceinline__ uint32_t smem_u32(const void* p) {
    uint32_t a;
    asm("{ .reg .u64 t; cvta.to.shared.u64 t, %1; cvt.u32.u64 %0, t; }" : "=r"(a) : "l"(p));
    return a;
}
__device__ __forceinline__ void cp_async16(uint32_t dst, const void* src) {
    asm volatile("cp.async.cg.shared.global [%0], [%1], 16;" :: "r"(dst), "l"(src) : "memory");
}
__device__ __forceinline__ void cp_async_wait_all() {
    asm volatile("cp.async.commit_group;\n cp.async.wait_group 0;" ::: "memory");
}
__device__ __forceinline__ void ldm_x4(uint32_t* r, uint32_t addr) {
    asm volatile("ldmatrix.sync.aligned.m8n8.x4.shared.b16 {%0,%1,%2,%3}, [%4];"
                 : "=r"(r[0]), "=r"(r[1]), "=r"(r[2]), "=r"(r[3]) : "r"(addr));
}
__device__ __forceinline__ void mma_bf16(float* c, const uint32_t* a, uint32_t b0, uint32_t b1) {
    asm volatile(
        "mma.sync.aligned.m16n8k16.row.col.f32.bf16.bf16.f32 "
        "{%0,%1,%2,%3}, {%4,%5,%6,%7}, {%8,%9}, {%0,%1,%2,%3};"
        : "+f"(c[0]), "+f"(c[1]), "+f"(c[2]), "+f"(c[3])
        : "r"(a[0]), "r"(a[1]), "r"(a[2]), "r"(a[3]), "r"(b0), "r"(b1));
}
__device__ __forceinline__ int labels_are_64(const int* p) {
    int ok = 1;
    #pragma unroll
    for (int q = 0; q < 32; ++q) ok &= (p[2 * q + 1] == 0);
    return ok;
}

// ---------------- kernel 0: init (sq, labels, bf16 convert, hardest=inf) ----------------
__global__ void __launch_bounds__(256) init_kernel(const float* __restrict__ E,
                                                   const void* __restrict__ labels_raw) {
    int warp = (blockIdx.x * blockDim.x + threadIdx.x) >> 5;  // 0..2047
    int lane = threadIdx.x & 31;
    int row0 = warp * 4;

    float4 e[4];
    #pragma unroll
    for (int r = 0; r < 4; ++r)
        e[r] = __ldg((const float4*)(E + (size_t)(row0 + r) * ND + lane * 4));

    #pragma unroll
    for (int r = 0; r < 4; ++r) {
        float s = e[r].x * e[r].x + e[r].y * e[r].y + e[r].z * e[r].z + e[r].w * e[r].w;
        #pragma unroll
        for (int o = 16; o > 0; o >>= 1) s += __shfl_xor_sync(0xffffffffu, s, o);
        __nv_bfloat16 b0[4] = {__float2bfloat16(e[r].x), __float2bfloat16(e[r].y),
                               __float2bfloat16(e[r].z), __float2bfloat16(e[r].w)};
        *(ushort4*)(g_eb + (size_t)(row0 + r) * ND + lane * 4) = *(ushort4*)b0;
        if (lane == 0) {
            g_sq[row0 + r] = s;
            g_hardest[row0 + r] = 0x7f800000u;  // +inf
        }
    }
    if (lane < 4) {
        int i = row0 + lane;
        const int* p32 = (const int*)labels_raw;
        g_labels[i] = labels_are_64(p32) ? (int)((const long long*)labels_raw)[i] : p32[i];
    }
    if (blockIdx.x == 0 && threadIdx.x == 0) {
        g_total = 0.0f; g_count = 0; g_pp_n = 0; g_done = 0;
    }
}

// ---------------- kernel 1: 128x256 tile, 64x64 warp tiles, masked min + harvest ----------------
extern __shared__ char smem_raw[];
__global__ void __launch_bounds__(256, 1) pass1_kernel() {
    // decode tile index b over {(it,jtc): it >= 2*jtc}; off(j) = 65j - j^2
    int b = blockIdx.x;
    int jtc = (int)((65.0f - sqrtf(65.0f * 65.0f - 4.0f * (float)b)) * 0.5f);
    while (65 * (jtc + 1) - (jtc + 1) * (jtc + 1) <= b) ++jtc;
    while (65 * jtc - jtc * jtc > b) --jtc;
    int it = 2 * jtc + (b - (65 * jtc - jtc * jtc));
    const bool allbelow = (it >= 2 * jtc + 2);   // tile strictly below diagonal

    const int t    = threadIdx.x;
    const int wid  = t >> 5;
    const int lane = t & 31;
    const int wm   = wid >> 2;      // 0..1  (m half: 64 rows)
    const int wn   = wid & 3;       // 0..3  (n quarter: 64 cols)
    const int g    = lane >> 2;     // group
    const int qt   = lane & 3;      // thread in quad
    uint32_t sbase = smem_u32(smem_raw);

    // fill A (128 rows) + B (256 rows) via cp.async
    {
        const char* srcA = (const char*)(g_eb + (size_t)(it * 128) * ND);
        #pragma unroll
        for (int q = 0; q < 8; ++q) {
            int idx = t + q * 256;           // 2048 chunks
            int row = idx >> 4, c16 = idx & 15;
            cp_async16(sbase + OFF_BUFA + row * (RSTRIDE * 2) + c16 * 16,
                       srcA + (size_t)row * 256 + c16 * 16);
        }
        const char* srcB = (const char*)(g_eb + (size_t)(jtc * 256) * ND);
        #pragma unroll
        for (int q = 0; q < 16; ++q) {
            int idx = t + q * 256;           // 4096 chunks
            int row = idx >> 4, c16 = idx & 15;
            cp_async16(sbase + OFF_BUFB + row * (RSTRIDE * 2) + c16 * 16,
                       srcB + (size_t)row * 256 + c16 * 16);
        }
    }

    if (t < 128) {
        *(int*)  (smem_raw + OFF_LI  + t * 4) = g_labels[it * 128 + t];
        *(float*)(smem_raw + OFF_SQI + t * 4) = g_sq[it * 128 + t];
    }
    *(int*)  (smem_raw + OFF_LJ  + t * 4) = g_labels[jtc * 256 + t];
    *(float*)(smem_raw + OFF_SQJ + t * 4) = g_sq[jtc * 256 + t];

    cp_async_wait_all();
    __syncthreads();

    // ldmatrix addressing (same fragment geometry as proven 64x32 layout, widened)
    uint32_t pA = sbase + OFF_BUFA +
                  ((wm * 64 + (lane & 15)) * RSTRIDE + (lane >> 4) * 8) * 2;
    uint32_t pB = sbase + OFF_BUFB +
                  ((wn * 64 + ((lane >> 4) * 8) + (lane & 7)) * RSTRIDE +
                   ((lane >> 3) & 1) * 8) * 2;

    float acc[4][8][4];   // [mi][ni][c], 64x64 per warp
    #pragma unroll
    for (int mi = 0; mi < 4; ++mi)
        #pragma unroll
        for (int ni = 0; ni < 8; ++ni)
            #pragma unroll
            for (int c = 0; c < 4; ++c) acc[mi][ni][c] = 0.0f;

    #pragma unroll
    for (int ks = 0; ks < 8; ++ks) {
        uint32_t afr[4][4], bfr[4][4];
        #pragma unroll
        for (int mi = 0; mi < 4; ++mi)
            ldm_x4(afr[mi], pA + mi * (16 * RSTRIDE * 2) + ks * 32);
        #pragma unroll
        for (int np = 0; np < 4; ++np)
            ldm_x4(bfr[np], pB + np * (16 * RSTRIDE * 2) + ks * 32);
        #pragma unroll
        for (int mi = 0; mi < 4; ++mi)
            #pragma unroll
            for (int ni = 0; ni < 8; ++ni)
                mma_bf16(acc[mi][ni], afr[mi],
                         bfr[ni >> 1][(ni & 1) * 2], bfr[ni >> 1][(ni & 1) * 2 + 1]);
    }

    // ---------------- epilogue: masked min (scratch+combine) + slim harvest ----------------
    int   rL[4][2], RG[4][2], liR[4][2];
    float sqiR[4][2];
    #pragma unroll
    for (int mi = 0; mi < 4; ++mi)
        #pragma unroll
        for (int h = 0; h < 2; ++h) {
            int r = wm * 64 + mi * 16 + h * 8 + g;
            rL[mi][h]   = r;
            RG[mi][h]   = it * 128 + r;
            liR[mi][h]  = *(const int*)  (smem_raw + OFF_LI  + r * 4);
            sqiR[mi][h] = *(const float*)(smem_raw + OFF_SQI + r * 4);
        }
    int   cL[8][2], CG[8][2], ljC[8][2];
    float sqjC[8][2];
    #pragma unroll
    for (int ni = 0; ni < 8; ++ni)
        #pragma unroll
        for (int cb = 0; cb < 2; ++cb) {
            int c = wn * 64 + ni * 8 + qt * 2 + cb;
            cL[ni][cb]   = c;
            CG[ni][cb]   = jtc * 256 + c;
            ljC[ni][cb]  = *(const int*)  (smem_raw + OFF_LJ  + c * 4);
            sqjC[ni][cb] = *(const float*)(smem_raw + OFF_SQJ + c * 4);
        }

    float rowmin[4][2], colmin[8][2];
    #pragma unroll
    for (int x = 0; x < 4; ++x)
        #pragma unroll
        for (int y = 0; y < 2; ++y) rowmin[x][y] = CUDART_INF_F;
    #pragma unroll
    for (int x = 0; x < 8; ++x)
        #pragma unroll
        for (int y = 0; y < 2; ++y) colmin[x][y] = CUDART_INF_F;

    #pragma unroll
    for (int mi = 0; mi < 4; ++mi)
        #pragma unroll
        for (int ni = 0; ni < 8; ++ni)
            #pragma unroll
            for (int h = 0; h < 2; ++h)
                #pragma unroll
                for (int cb = 0; cb < 2; ++cb) {
                    float d = fmaf(-2.0f, acc[mi][ni][h * 2 + cb],
                                   sqiR[mi][h] + sqjC[ni][cb]);
                    if (ljC[ni][cb] != liR[mi][h]) {
                        rowmin[mi][h]  = fminf(rowmin[mi][h], d);
                        colmin[ni][cb] = fminf(colmin[ni][cb], d);
                    } else if (allbelow || RG[mi][h] > CG[ni][cb]) {
                        // positive pair (rare): emit both orientations once
                        unsigned db = __float_as_uint(fmaxf(d, 0.0f));
                        int pos = atomicAdd(&g_pp_n, 2);
                        if (pos <= PPCAP - 2) {
                            g_pp[pos]     = ((unsigned long long)(unsigned)RG[mi][h] << 32) | db;
                            g_pp[pos + 1] = ((unsigned long long)(unsigned)CG[ni][cb] << 32) | db;
                        }
                    }
                }

    // rows: quad-reduce -> scratch[row][wn]
    #pragma unroll
    for (int mi = 0; mi < 4; ++mi)
        #pragma unroll
        for (int h = 0; h < 2; ++h) {
            float v = rowmin[mi][h];
            v = fminf(v, __shfl_xor_sync(0xffffffffu, v, 1));
            v = fminf(v, __shfl_xor_sync(0xffffffffu, v, 2));
            if (qt == 0)
                *(float*)(smem_raw + OFF_SCR_R + (rL[mi][h] * 4 + wn) * 4) = v;
        }
    // cols: group-reduce -> scratch[col][wm]
    #pragma unroll
    for (int ni = 0; ni < 8; ++ni)
        #pragma unroll
        for (int cb = 0; cb < 2; ++cb) {
            float v = colmin[ni][cb];
            v = fminf(v, __shfl_xor_sync(0xffffffffu, v, 4));
            v = fminf(v, __shfl_xor_sync(0xffffffffu, v, 8));
            v = fminf(v, __shfl_xor_sync(0xffffffffu, v, 16));
            if (lane < 4)
                *(float*)(smem_raw + OFF_SCR_C + (cL[ni][cb] * 2 + wm) * 4) = v;
        }
    __syncthreads();

    if (t < 128) {
        const float* sr = (const float*)(smem_raw + OFF_SCR_R) + t * 4;
        float m = fminf(fminf(sr[0], sr[1]), fminf(sr[2], sr[3]));
        atomicMin(&g_hardest[it * 128 + t], __float_as_uint(fmaxf(m, 0.0f)));
    }
    {
        const float* sc = (const float*)(smem_raw + OFF_SCR_C) + t * 2;
        float m = fminf(sc[0], sc[1]);
        atomicMin(&g_hardest[jtc * 256 + t], __float_as_uint(fmaxf(m, 0.0f)));
    }
}

// ---------------- kernel 2: per-entry triplet loss, block-reduced + last-block finalize ----------------
__global__ void __launch_bounds__(256) pairloss_kernel(float* out, int out_n) {
    __shared__ float s_ls[8];
    __shared__ int   s_lc[8];
    int n = g_pp_n;
    if (n > PPCAP) n = PPCAP;
    int lane  = threadIdx.x & 31;
    int warpl = threadIdx.x >> 5;

    float ls = 0.0f;
    int   lc = 0;
    for (int i = blockIdx.x * blockDim.x + threadIdx.x; i < n;
         i += gridDim.x * blockDim.x) {
        unsigned long long e = g_pp[i];
        int   a  = (int)(e >> 32);
        float dp = __uint_as_float((unsigned)e);
        float hn = __uint_as_float(g_hardest[a]);   // +inf => no negative
        if (hn < dp) {
            ls += fmaxf(dp - hn + MARGIN, 0.0f);
            lc += 1;
        }
    }
    #pragma unroll
    for (int o = 16; o > 0; o >>= 1) {
        ls += __shfl_xor_sync(0xffffffffu, ls, o);
        lc += __shfl_xor_sync(0xffffffffu, lc, o);
    }
    if (lane == 0) { s_ls[warpl] = ls; s_lc[warpl] = lc; }
    __syncthreads();
    if (threadIdx.x == 0) {
        float bls = 0.0f;
        int   blc = 0;
        #pragma unroll
        for (int w = 0; w < 8; ++w) { bls += s_ls[w]; blc += s_lc[w]; }
        if (blc) {
            atomicAdd(&g_total, bls);
            atomicAdd(&g_count, blc);
        }
    }

    // last-block finalization
    __syncthreads();
    __threadfence();
    __shared__ int is_last;
    if (threadIdx.x == 0)
        is_last = (atomicAdd(&g_done, 1) == (int)gridDim.x - 1);
    __syncthreads();
    if (is_last) {
        for (int i = threadIdx.x; i < out_n; i += blockDim.x) {
            if (i == 0) {
                int c = g_count;
                out[0] = g_total / (float)(c > 0 ? c : 1);
            } else if (i == 1) {
                out[1] = (float)g_count;
            } else {
                out[i] = 0.0f;
            }
        }
    }
}

extern "C" void kernel_launch(void* const* d_in, const int* in_sizes, int n_in,
                              void* d_out, int out_size) {
    const float* E   = (const float*)d_in[0];
    const void*  lab = d_in[1];

    cudaFuncSetAttribute(pass1_kernel, cudaFuncAttributeMaxDynamicSharedMemorySize, SMEM_SZ);

    init_kernel<<<NB / 32, 256>>>(E, lab);          // 256 blocks, 4 rows/warp
    pass1_kernel<<<NTILE, 256, SMEM_SZ>>>();
    pairloss_kernel<<<PL_GRID, 256>>>((float*)d_out, out_size);
}

// round 16
// speedup vs baseline: 1.4891x; 1.4891x over previous
#include <cuda_runtime.h>
#include <cuda_bf16.h>
#include <math_constants.h>
#include <cstdint>

#define NB      8192
#define ND      128
#define TM      128
#define MARGIN  1.0f
#define NT      (NB / TM)            // 64
#define NTRI    (NT * (NT + 1) / 2)  // 2080

// smem tile: 128 rows x 136 halves (272B padded rows -> conflict-free ldmatrix)
#define RSTRIDE 136
#define BUFB    (128 * RSTRIDE * 2)  // 34816 bytes per operand buffer

#define OFF_LI    0
#define OFF_LJ    512
#define OFF_SQI   1024
#define OFF_SQJ   1536
#define OFF_SCR_R 2048              // float [128][4]
#define OFF_SCR_C 4096              // float [128][2]
#define OFF_BUF   5120              // 2 x BUFB: A, B
#define SMEM_SZ   (OFF_BUF + 2 * BUFB)   // 74752 -> 2 CTAs/SM

#define PPCAP   131072               // positive-pair entry capacity
#define PL_GRID 296                  // pairloss blocks (2 per SM)

// -------- scratch in device globals (no allocation allowed) --------
__device__ unsigned int g_hardest[NB];
__device__ float        g_sq[NB];
__device__ int          g_labels[NB];
__device__ float        g_total;
__device__ int          g_count;
__device__ int          g_done;
__device__ __nv_bfloat16 g_eb[NB * ND];          // bf16 embeddings
__device__ unsigned long long g_pp[PPCAP];       // packed (anchor<<32 | f32bits(d_pos))
__device__ int          g_pp_n;

__device__ __forceinline__ uint32_t smem_u32(const void* p) {
    uint32_t a;
    asm("{ .reg .u64 t; cvta.to.shared.u64 t, %1; cvt.u32.u64 %0, t; }" : "=r"(a) : "l"(p));
    return a;
}
__device__ __forceinline__ void cp_async16(uint32_t dst, const void* src) {
    asm volatile("cp.async.cg.shared.global [%0], [%1], 16;" :: "r"(dst), "l"(src) : "memory");
}
__device__ __forceinline__ void cp_async_wait_all() {
    asm volatile("cp.async.commit_group;\n cp.async.wait_group 0;" ::: "memory");
}
__device__ __forceinline__ void ldm_x4(uint32_t* r, uint32_t addr) {
    asm volatile("ldmatrix.sync.aligned.m8n8.x4.shared.b16 {%0,%1,%2,%3}, [%4];"
                 : "=r"(r[0]), "=r"(r[1]), "=r"(r[2]), "=r"(r[3]) : "r"(addr));
}
__device__ __forceinline__ void mma_bf16(float* c, const uint32_t* a, uint32_t b0, uint32_t b1) {
    asm volatile(
        "mma.sync.aligned.m16n8k16.row.col.f32.bf16.bf16.f32 "
        "{%0,%1,%2,%3}, {%4,%5,%6,%7}, {%8,%9}, {%0,%1,%2,%3};"
        : "+f"(c[0]), "+f"(c[1]), "+f"(c[2]), "+f"(c[3])
        : "r"(a[0]), "r"(a[1]), "r"(a[2]), "r"(a[3]), "r"(b0), "r"(b1));
}
__device__ __forceinline__ int labels_are_64(const int* p) {
    int ok = 1;
    #pragma unroll
    for (int q = 0; q < 32; ++q) ok &= (p[2 * q + 1] == 0);
    return ok;
}

// ---------------- kernel 0: init (sq, labels, bf16 convert, hardest=inf) ----------------
__global__ void __launch_bounds__(256) init_kernel(const float* __restrict__ E,
                                                   const void* __restrict__ labels_raw) {
    int warp = (blockIdx.x * blockDim.x + threadIdx.x) >> 5;  // 0..2047
    int lane = threadIdx.x & 31;
    int row0 = warp * 4;

    float4 e[4];
    #pragma unroll
    for (int r = 0; r < 4; ++r)
        e[r] = __ldg((const float4*)(E + (size_t)(row0 + r) * ND + lane * 4));

    #pragma unroll
    for (int r = 0; r < 4; ++r) {
        float s = e[r].x * e[r].x + e[r].y * e[r].y + e[r].z * e[r].z + e[r].w * e[r].w;
        #pragma unroll
        for (int o = 16; o > 0; o >>= 1) s += __shfl_xor_sync(0xffffffffu, s, o);
        __nv_bfloat16 b0[4] = {__float2bfloat16(e[r].x), __float2bfloat16(e[r].y),
                               __float2bfloat16(e[r].z), __float2bfloat16(e[r].w)};
        *(ushort4*)(g_eb + (size_t)(row0 + r) * ND + lane * 4) = *(ushort4*)b0;
        if (lane == 0) {
            g_sq[row0 + r] = s;
            g_hardest[row0 + r] = 0x7f800000u;  // +inf
        }
    }
    if (lane < 4) {
        int i = row0 + lane;
        const int* p32 = (const int*)labels_raw;
        g_labels[i] = labels_are_64(p32) ? (int)((const long long*)labels_raw)[i] : p32[i];
    }
    if (blockIdx.x == 0 && threadIdx.x == 0) {
        g_total = 0.0f; g_count = 0; g_pp_n = 0; g_done = 0;
    }
}

// ---------------- kernel 1: triangular tile, bf16 HMMA + masked min + mask-deferred harvest ----------------
extern __shared__ char smem_raw[];
__global__ void __launch_bounds__(256, 2) pass1_kernel() {
    // decode triangular block index b = it*(it+1)/2 + jt, jt <= it
    int b = blockIdx.x;
    int it = (int)((sqrtf(8.0f * (float)b + 1.0f) - 1.0f) * 0.5f);
    while ((it + 1) * (it + 2) / 2 <= b) ++it;
    while (it * (it + 1) / 2 > b) --it;
    int jt = b - it * (it + 1) / 2;
    const int diag = (it == jt);

    const int t    = threadIdx.x;
    const int wid  = t >> 5;
    const int lane = t & 31;
    const int wm   = wid >> 2;      // 0..1  (m half)
    const int wn   = wid & 3;       // 0..3  (n quarter)
    const int g    = lane >> 2;     // group
    const int qt   = lane & 3;      // thread in quad
    uint32_t sbase = smem_u32(smem_raw);

    // fill operand buffers with cp.async (skip B for diagonal tiles: A == B)
    const int nbuf = diag ? 1 : 2;
    for (int buf = 0; buf < nbuf; ++buf) {
        const char* src = (const char*)(g_eb + (size_t)((buf ? jt : it) * TM) * ND);
        uint32_t dst = sbase + OFF_BUF + buf * BUFB;
        #pragma unroll
        for (int q = 0; q < 8; ++q) {
            int idx = t + q * 256;           // 2048 chunks of 16B
            int row = idx >> 4, c16 = idx & 15;
            cp_async16(dst + row * (RSTRIDE * 2) + c16 * 16,
                       src + (size_t)row * 256 + c16 * 16);
        }
    }

    if (t < 128) {
        *(int*)  (smem_raw + OFF_LI  + t * 4) = g_labels[it * TM + t];
        *(float*)(smem_raw + OFF_SQI + t * 4) = g_sq[it * TM + t];
    } else {
        int c = t - 128;
        *(int*)  (smem_raw + OFF_LJ  + c * 4) = g_labels[jt * TM + c];
        *(float*)(smem_raw + OFF_SQJ + c * 4) = g_sq[jt * TM + c];
    }

    cp_async_wait_all();
    __syncthreads();

    // ldmatrix addressing (proven layout)
    uint32_t pA = sbase + OFF_BUF +
                  ((wm * 64 + (lane & 15)) * RSTRIDE + (lane >> 4) * 8) * 2;
    uint32_t pB = sbase + OFF_BUF + (diag ? 0 : BUFB) +
                  ((wn * 32 + ((lane >> 4) * 8) + (lane & 7)) * RSTRIDE +
                   ((lane >> 3) & 1) * 8) * 2;

    float acc[4][4][4];   // [mi][ni][c]
    #pragma unroll
    for (int mi = 0; mi < 4; ++mi)
        #pragma unroll
        for (int ni = 0; ni < 4; ++ni)
            #pragma unroll
            for (int c = 0; c < 4; ++c) acc[mi][ni][c] = 0.0f;

    #pragma unroll
    for (int ks = 0; ks < 8; ++ks) {
        uint32_t afr[4][4], bfr[2][4];
        #pragma unroll
        for (int mi = 0; mi < 4; ++mi)
            ldm_x4(afr[mi], pA + mi * (16 * RSTRIDE * 2) + ks * 32);
        #pragma unroll
        for (int np = 0; np < 2; ++np)
            ldm_x4(bfr[np], pB + np * (16 * RSTRIDE * 2) + ks * 32);
        #pragma unroll
        for (int mi = 0; mi < 4; ++mi)
            #pragma unroll
            for (int ni = 0; ni < 4; ++ni)
                mma_bf16(acc[mi][ni], afr[mi],
                         bfr[ni >> 1][(ni & 1) * 2], bfr[ni >> 1][(ni & 1) * 2 + 1]);
    }

    // ---------------- epilogue: masked min with bit-mask positive recording ----------------
    int   liR[4][2];  float sqiR[4][2];
    int   ljC[4][2];  float sqjC[4][2];
    #pragma unroll
    for (int mi = 0; mi < 4; ++mi)
        #pragma unroll
        for (int h = 0; h < 2; ++h) {
            int R = wm * 64 + mi * 16 + h * 8 + g;
            liR[mi][h]  = *(const int*)  (smem_raw + OFF_LI  + R * 4);
            sqiR[mi][h] = *(const float*)(smem_raw + OFF_SQI + R * 4);
        }
    #pragma unroll
    for (int ni = 0; ni < 4; ++ni)
        #pragma unroll
        for (int cb = 0; cb < 2; ++cb) {
            int C = wn * 32 + ni * 8 + qt * 2 + cb;
            ljC[ni][cb]  = *(const int*)  (smem_raw + OFF_LJ  + C * 4);
            sqjC[ni][cb] = *(const float*)(smem_raw + OFF_SQJ + C * 4);
        }

    float rowmin[4][2], colmin[4][2];
    #pragma unroll
    for (int x = 0; x < 4; ++x)
        #pragma unroll
        for (int y = 0; y < 2; ++y) { rowmin[x][y] = CUDART_INF_F; colmin[x][y] = CUDART_INF_F; }

    unsigned long long pmask = 0ull;   // bit per (mi,ni,h,cb) site where label matches
    #pragma unroll
    for (int mi = 0; mi < 4; ++mi)
        #pragma unroll
        for (int ni = 0; ni < 4; ++ni)
            #pragma unroll
            for (int h = 0; h < 2; ++h)
                #pragma unroll
                for (int cb = 0; cb < 2; ++cb) {
                    float d = fmaf(-2.0f, acc[mi][ni][h * 2 + cb],
                                   sqiR[mi][h] + sqjC[ni][cb]);
                    bool pos = (ljC[ni][cb] == liR[mi][h]);
                    pmask |= ((unsigned long long)pos) << (mi * 16 + ni * 4 + h * 2 + cb);
                    float m = pos ? CUDART_INF_F : d;
                    rowmin[mi][h]  = fminf(rowmin[mi][h], m);
                    colmin[ni][cb] = fminf(colmin[ni][cb], m);
                }

    // deferred harvest: rare path, executed ~0.12x per thread on average.
    // Recompute the dot in fp32 from the resident smem tiles (pre-barrier).
    while (pmask) {
        int site = __ffsll(pmask) - 1;
        pmask &= pmask - 1;
        int cb = site & 1, h = (site >> 1) & 1, ni = (site >> 2) & 3, mi = site >> 4;
        int r = wm * 64 + mi * 16 + h * 8 + g;
        int c = wn * 32 + ni * 8 + qt * 2 + cb;
        int R = it * TM + r, C = jt * TM + c;
        if (diag && R <= C) continue;    // self + upper-diag dedup
        const __nv_bfloat16* ar = (const __nv_bfloat16*)(smem_raw + OFF_BUF + r * RSTRIDE * 2);
        const __nv_bfloat16* br = (const __nv_bfloat16*)(smem_raw + OFF_BUF +
                                                         (diag ? 0 : BUFB) + c * RSTRIDE * 2);
        float dot = 0.0f;
        #pragma unroll 16
        for (int k = 0; k < ND; k += 2) {
            float2 a2 = __bfloat1622float2(*(const __nv_bfloat162*)(ar + k));
            float2 b2 = __bfloat1622float2(*(const __nv_bfloat162*)(br + k));
            dot = fmaf(a2.x, b2.x, dot);
            dot = fmaf(a2.y, b2.y, dot);
        }
        float sqi = *(const float*)(smem_raw + OFF_SQI + r * 4);
        float sqj = *(const float*)(smem_raw + OFF_SQJ + c * 4);
        unsigned db = __float_as_uint(fmaxf(fmaf(-2.0f, dot, sqi + sqj), 0.0f));
        int pos2 = atomicAdd(&g_pp_n, 2);
        if (pos2 <= PPCAP - 2) {
            g_pp[pos2]     = ((unsigned long long)(unsigned)R << 32) | db;
            g_pp[pos2 + 1] = ((unsigned long long)(unsigned)C << 32) | db;
        }
    }

    // proven scratch + combine epilogue
    #pragma unroll
    for (int mi = 0; mi < 4; ++mi)
        #pragma unroll
        for (int h = 0; h < 2; ++h) {
            float v = rowmin[mi][h];
            v = fminf(v, __shfl_xor_sync(0xffffffffu, v, 1));
            v = fminf(v, __shfl_xor_sync(0xffffffffu, v, 2));
            if (qt == 0) {
                int r = wm * 64 + mi * 16 + h * 8 + g;
                *(float*)(smem_raw + OFF_SCR_R + (r * 4 + wn) * 4) = v;
            }
        }
    #pragma unroll
    for (int ni = 0; ni < 4; ++ni)
        #pragma unroll
        for (int cb = 0; cb < 2; ++cb) {
            float v = colmin[ni][cb];
            v = fminf(v, __shfl_xor_sync(0xffffffffu, v, 4));
            v = fminf(v, __shfl_xor_sync(0xffffffffu, v, 8));
            v = fminf(v, __shfl_xor_sync(0xffffffffu, v, 16));
            if (lane < 4) {
                int c = wn * 32 + ni * 8 + qt * 2 + cb;
                *(float*)(smem_raw + OFF_SCR_C + (c * 2 + wm) * 4) = v;
            }
        }
    __syncthreads();

    if (t < 128) {
        const float* sr = (const float*)(smem_raw + OFF_SCR_R) + t * 4;
        float m = fminf(fminf(sr[0], sr[1]), fminf(sr[2], sr[3]));
        atomicMin(&g_hardest[it * TM + t], __float_as_uint(fmaxf(m, 0.0f)));
    } else {
        int c = t - 128;
        const float* sc = (const float*)(smem_raw + OFF_SCR_C) + c * 2;
        float m = fminf(sc[0], sc[1]);
        atomicMin(&g_hardest[jt * TM + c], __float_as_uint(fmaxf(m, 0.0f)));
    }
}

// ---------------- kernel 2: per-entry triplet loss, block-reduced + last-block finalize ----------------
__global__ void __launch_bounds__(256) pairloss_kernel(float* out, int out_n) {
    __shared__ float s_ls[8];
    __shared__ int   s_lc[8];
    int n = g_pp_n;
    if (n > PPCAP) n = PPCAP;
    int lane  = threadIdx.x & 31;
    int warpl = threadIdx.x >> 5;

    float ls = 0.0f;
    int   lc = 0;
    for (int i = blockIdx.x * blockDim.x + threadIdx.x; i < n;
         i += gridDim.x * blockDim.x) {
        unsigned long long e = g_pp[i];
        int   a  = (int)(e >> 32);
        float dp = __uint_as_float((unsigned)e);
        float hn = __uint_as_float(g_hardest[a]);   // +inf => no negative
        if (hn < dp) {
            ls += fmaxf(dp - hn + MARGIN, 0.0f);
            lc += 1;
        }
    }
    #pragma unroll
    for (int o = 16; o > 0; o >>= 1) {
        ls += __shfl_xor_sync(0xffffffffu, ls, o);
        lc += __shfl_xor_sync(0xffffffffu, lc, o);
    }
    if (lane == 0) { s_ls[warpl] = ls; s_lc[warpl] = lc; }
    __syncthreads();
    if (threadIdx.x == 0) {
        float bls = 0.0f;
        int   blc = 0;
        #pragma unroll
        for (int w = 0; w < 8; ++w) { bls += s_ls[w]; blc += s_lc[w]; }
        if (blc) {
            atomicAdd(&g_total, bls);
            atomicAdd(&g_count, blc);
        }
    }

    // last-block finalization
    __syncthreads();
    __threadfence();
    __shared__ int is_last;
    if (threadIdx.x == 0)
        is_last = (atomicAdd(&g_done, 1) == (int)gridDim.x - 1);
    __syncthreads();
    if (is_last) {
        for (int i = threadIdx.x; i < out_n; i += blockDim.x) {
            if (i == 0) {
                int c = g_count;
                out[0] = g_total / (float)(c > 0 ? c : 1);
            } else if (i == 1) {
                out[1] = (float)g_count;
            } else {
                out[i] = 0.0f;
            }
        }
    }
}

extern "C" void kernel_launch(void* const* d_in, const int* in_sizes, int n_in,
                              void* d_out, int out_size) {
    const float* E   = (const float*)d_in[0];
    const void*  lab = d_in[1];

    cudaFuncSetAttribute(pass1_kernel, cudaFuncAttributeMaxDynamicSharedMemorySize, SMEM_SZ);

    init_kernel<<<NB / 32, 256>>>(E, lab);          // 256 blocks, 4 rows/warp
    pass1_kernel<<<NTRI, 256, SMEM_SZ>>>();
    pairloss_kernel<<<PL_GRID, 256>>>((float*)d_out, out_size);
}